// round 10
// baseline (speedup 1.0000x reference)
#include <cuda_runtime.h>
#include <cuda_bf16.h>

#define KB    64      // boxes
#define GRID  128     // block b handles striped rows {b, b+128, b+256, b+384}
#define TPB   1024    // 32 warps: warp w -> row (w>>3), 64-px span (w&7)

__device__ double       g_acc[2];   // zero at load; last block resets -> zero each replay
__device__ unsigned int g_cnt;      // wraps back to 0 every run (deterministic)

__device__ __forceinline__ float sqrt_approx(float x) {
    float r; asm("sqrt.approx.f32 %0, %1;" : "=f"(r) : "f"(x)); return r;
}

__global__ __launch_bounds__(TPB) void lz_fused_kernel(
    const float* __restrict__ cm,      // center_maps (batch 0 = first 262144)
    const float* __restrict__ smap,    // scale_maps (batch 0)
    const float* __restrict__ ann,     // annotations (batch 0 = 64 float4)
    const void*  __restrict__ stridep, // stride scalar (int32 or float32)
    float* __restrict__ out)
{
    __shared__ float r_c[32], r_s[32];

    const int tid  = threadIdx.x;
    const int b    = blockIdx.x;
    const int lane = tid & 31;
    const int w    = tid >> 5;          // warp 0..31
    const int rr   = w >> 3;            // which striped row
    const int sp   = w & 7;             // 64-px span within row

    const int y    = b + (rr << 7);     // this warp's row
    const int wxa  = sp << 6;           // warp first x
    const int x0   = wxa + (lane << 1); // thread's first pixel
    const float fx0 = (float)x0;
    const int   wxb = wxa + 63;

    // ---- issue ALL independent loads at cycle 0 (parallel round trips) ----
    const int gq = y * 256 + (x0 >> 1);            // float2 index into maps
    const float2 cm2 = ((const float2*)cm)[gq];    // unconditional: overlaps ann latency
    const float4 ab0 = ((const float4*)ann)[lane];
    const float4 ab1 = ((const float4*)ann)[lane + 32];

    // ---- stride (uniform tiny load) ----
    float stridef = 4.0f;
    if (stridep) {
        int iv = ((const int*)stridep)[0];
        stridef = (iv > 0 && iv <= 65536) ? (float)iv : __int_as_float(iv);
    }
    const float inv = 1.0f / stridef;

    // ---- each lane owns boxes {lane, lane+32}: predicates + ballots (no smem) ----
    unsigned mg[2], ms[2];
    {
        // half 0
        int x1 = (int)floorf(ab0.x * inv), y1 = (int)floorf(ab0.y * inv);
        int x2 = (int)floorf(ab0.z * inv), y2 = (int)floorf(ab0.w * inv);
        int cx = (x1 + x2) >> 1, cy = (y1 + y2) >> 1, dyo = y - cy;
        bool pg = (y >= y1) && (y < y2) && (x1 <= wxb) && (x2 > wxa);
        bool ps = ((unsigned)(dyo + 2) <= 4u) && ((unsigned)(cx + dyo - wxa) <= 63u);
        mg[0] = __ballot_sync(0xffffffffu, pg);
        ms[0] = __ballot_sync(0xffffffffu, ps);
        // half 1
        x1 = (int)floorf(ab1.x * inv); y1 = (int)floorf(ab1.y * inv);
        x2 = (int)floorf(ab1.z * inv); y2 = (int)floorf(ab1.w * inv);
        cx = (x1 + x2) >> 1; cy = (y1 + y2) >> 1; dyo = y - cy;
        pg = (y >= y1) && (y < y2) && (x1 <= wxb) && (x2 > wxa);
        ps = ((unsigned)(dyo + 2) <= 4u) && ((unsigned)(cx + dyo - wxa) <= 63u);
        mg[1] = __ballot_sync(0xffffffffu, pg);
        ms[1] = __ballot_sync(0xffffffffu, ps);
    }

    float csum = 0.f, ssum = 0.f;

    if ((mg[0] | mg[1] | ms[0] | ms[1]) != 0u) {
        float gmax[2] = {0.f,0.f};
        float blog[2] = {0.f,0.f};
        int   maxj[2] = {-1,-1};
        int   posm = 0, cenm = 0;
        const float fy = (float)y;

        #pragma unroll
        for (int h = 0; h < 2; h++) {
            const float4 abh = h ? ab1 : ab0;
            unsigned m = mg[h];
            while (m) {
                const int src = __ffs(m) - 1; m &= m - 1;
                // broadcast raw annotation, recompute params locally
                const float a0 = __shfl_sync(0xffffffffu, abh.x, src);
                const float a1 = __shfl_sync(0xffffffffu, abh.y, src);
                const float a2 = __shfl_sync(0xffffffffu, abh.z, src);
                const float a3 = __shfl_sync(0xffffffffu, abh.w, src);
                const int x1 = (int)floorf(a0 * inv), y1 = (int)floorf(a1 * inv);
                const int x2 = (int)floorf(a2 * inv), y2 = (int)floorf(a3 * inv);
                const int cx = (x1 + x2) >> 1, cy = (y1 + y2) >> 1;
                const float A = (float)(x1 + cx);
                const float C = -0.5f / sqrt_approx((float)cx*(float)cx + (float)cy*(float)cy);
                const float dy = fy - (float)(y1 + cy);
                const float dy2 = dy * dy;
                const float fx1 = (float)x1, fx2 = (float)x2;
                #pragma unroll
                for (int i = 0; i < 2; i++) {
                    const float fx = fx0 + (float)i;
                    if (fx >= fx1 && fx < fx2) {
                        posm |= (1 << i);
                        const float dx = fx - A;
                        const float d  = sqrt_approx(fmaf(dx, dx, dy2));
                        gmax[i] = fmaxf(gmax[i], __expf(C * d));
                    }
                }
            }
            m = ms[h];
            while (m) {
                const int src = __ffs(m) - 1; m &= m - 1;
                const float a0 = __shfl_sync(0xffffffffu, abh.x, src);
                const float a1 = __shfl_sync(0xffffffffu, abh.y, src);
                const float a2 = __shfl_sync(0xffffffffu, abh.z, src);
                const float a3 = __shfl_sync(0xffffffffu, abh.w, src);
                const int x1 = (int)floorf(a0 * inv), y1 = (int)floorf(a1 * inv);
                const int x2 = (int)floorf(a2 * inv), y2 = (int)floorf(a3 * inv);
                const int cx = (x1 + x2) >> 1, cy = (y1 + y2) >> 1;
                const int dyo = y - cy;
                const int t = cx + dyo - x0;
                if ((unsigned)t <= 1u) {
                    const int k = src + (h << 5);
                    const int j = (dyo + 2) * KB + k;       // last-write-wins order
                    if (j > maxj[t]) { maxj[t] = j; blog[t] = __logf((float)(y2 - y1)); }
                    if (dyo == 0) cenm |= (1 << t);
                }
            }
        }

        const float pv[2] = {cm2.x, cm2.y};
        #pragma unroll
        for (int i = 0; i < 2; i++) {
            const float p = fminf(fmaxf(pv[i], 1e-4f), 0.9999f);
            if (cenm & (1 << i)) {
                const float q = 1.0f - p;
                csum += q * q * (-__logf(p));                    // ALPHA=1, GAMMA=2
            } else if (posm & (1 << i)) {
                float q = 1.0f - gmax[i];
                float wgt = q * q; wgt = wgt * wgt;              // BETA=4
                csum += wgt * p * p * (-__logf(1.0f - p));
            }
            if (maxj[i] >= 0) {
                const float d = fabsf(blog[i] - smap[(size_t)gq * 2 + i]);
                ssum += (d <= 1.0f) ? 0.5f * d * d : (d - 0.5f);
            }
        }
    }

    // ---- block reduce (single barrier) ----
    #pragma unroll
    for (int off = 16; off; off >>= 1) {
        csum += __shfl_down_sync(0xffffffffu, csum, off);
        ssum += __shfl_down_sync(0xffffffffu, ssum, off);
    }
    if (lane == 0) { r_c[w] = csum; r_s[w] = ssum; }
    __syncthreads();
    if (tid < 32) {
        csum = r_c[tid]; ssum = r_s[tid];
        #pragma unroll
        for (int off = 16; off; off >>= 1) {
            csum += __shfl_down_sync(0xffffffffu, csum, off);
            ssum += __shfl_down_sync(0xffffffffu, ssum, off);
        }
        if (tid == 0) {
            // fire-and-forget relaxed reductions (compile to RED)
            atomicAdd(&g_acc[0], (double)csum);
            atomicAdd(&g_acc[1], (double)ssum);
            // release-inc replaces __threadfence + relaxed inc:
            // prior REDs are made visible before this inc is visible
            unsigned old;
            asm volatile("atom.release.gpu.global.inc.u32 %0, [%1], %2;"
                         : "=r"(old)
                         : "l"(&g_cnt), "r"((unsigned)(GRID - 1))
                         : "memory");
            if (old == GRID - 1) {
                // acquire loads pair with the release-incs: all adds visible
                double c2, s2;
                asm volatile("ld.acquire.gpu.global.f64 %0, [%1];"
                             : "=d"(c2) : "l"(&g_acc[0]) : "memory");
                asm volatile("ld.acquire.gpu.global.f64 %0, [%1];"
                             : "=d"(s2) : "l"(&g_acc[1]) : "memory");
                out[0] = (float)(c2 * (1.0 / 64.0));
                out[1] = (float)(s2 * (1.0 / 64.0));
                g_acc[0] = 0.0;     // reset for next replay (kernel boundary orders this)
                g_acc[1] = 0.0;
            }
        }
    }
}

extern "C" void kernel_launch(void* const* d_in, const int* in_sizes, int n_in,
                              void* d_out, int out_size) {
    const float* cm   = (const float*)d_in[0];
    const float* sm   = (const float*)d_in[1];
    const float* ann  = (const float*)d_in[2];
    const void*  strp = (n_in > 3) ? d_in[3] : nullptr;
    float* out = (float*)d_out;

    lz_fused_kernel<<<GRID, TPB>>>(cm, sm, ann, strp, out);
}

// round 11
// speedup vs baseline: 1.0029x; 1.0029x over previous
#include <cuda_runtime.h>
#include <cuda_bf16.h>

#define KB    64      // boxes
#define GRID  128     // block b handles striped rows {b, b+128, b+256, b+384}
#define TPB   512     // 16 warps: warp w -> row (w>>2), 128-px span (w&3)

__device__ double       g_acc[2];   // zero at load; last block resets -> zero each replay
__device__ unsigned int g_cnt;      // wraps back to 0 every run (deterministic)

__device__ __forceinline__ float sqrt_approx(float x) {
    float r; asm("sqrt.approx.f32 %0, %1;" : "=f"(r) : "f"(x)); return r;
}

__global__ __launch_bounds__(TPB) void lz_fused_kernel(
    const float* __restrict__ cm,      // center_maps (batch 0 = first 262144)
    const float* __restrict__ smap,    // scale_maps (batch 0)
    const float* __restrict__ ann,     // annotations (batch 0 = 64 float4)
    const void*  __restrict__ stridep, // stride scalar (int32 or float32)
    float* __restrict__ out)
{
    __shared__ float r_c[16], r_s[16];

    const int tid  = threadIdx.x;
    const int b    = blockIdx.x;
    const int lane = tid & 31;
    const int w    = tid >> 5;          // warp 0..15
    const int rr   = w >> 2;            // which striped row (0..3)
    const int sp   = w & 3;             // 128-px span within row

    const int y    = b + (rr << 7);     // this warp's row
    const int wxa  = sp << 7;           // warp first x
    const int x0   = wxa + (lane << 2); // thread's first pixel (4 px/thread)
    const float fx0 = (float)x0;
    const int   wxb = wxa + 127;

    // ---- issue ALL independent loads at cycle 0 (parallel round trips) ----
    const int gq = y * 128 + (x0 >> 2);            // float4 index into maps
    const float4 cm4 = ((const float4*)cm)[gq];    // unconditional: overlaps ann latency
    const float4 ab0 = ((const float4*)ann)[lane];
    const float4 ab1 = ((const float4*)ann)[lane + 32];

    // ---- stride (uniform tiny load) ----
    float stridef = 4.0f;
    if (stridep) {
        int iv = ((const int*)stridep)[0];
        stridef = (iv > 0 && iv <= 65536) ? (float)iv : __int_as_float(iv);
    }
    const float inv = 1.0f / stridef;

    // ---- each lane owns boxes {lane, lane+32}: predicates + ballots (no smem) ----
    unsigned mg[2], ms[2];
    {
        // half 0
        int x1 = (int)floorf(ab0.x * inv), y1 = (int)floorf(ab0.y * inv);
        int x2 = (int)floorf(ab0.z * inv), y2 = (int)floorf(ab0.w * inv);
        int cx = (x1 + x2) >> 1, cy = (y1 + y2) >> 1, dyo = y - cy;
        bool pg = (y >= y1) && (y < y2) && (x1 <= wxb) && (x2 > wxa);
        bool ps = ((unsigned)(dyo + 2) <= 4u) && ((unsigned)(cx + dyo - wxa) <= 127u);
        mg[0] = __ballot_sync(0xffffffffu, pg);
        ms[0] = __ballot_sync(0xffffffffu, ps);
        // half 1
        x1 = (int)floorf(ab1.x * inv); y1 = (int)floorf(ab1.y * inv);
        x2 = (int)floorf(ab1.z * inv); y2 = (int)floorf(ab1.w * inv);
        cx = (x1 + x2) >> 1; cy = (y1 + y2) >> 1; dyo = y - cy;
        pg = (y >= y1) && (y < y2) && (x1 <= wxb) && (x2 > wxa);
        ps = ((unsigned)(dyo + 2) <= 4u) && ((unsigned)(cx + dyo - wxa) <= 127u);
        mg[1] = __ballot_sync(0xffffffffu, pg);
        ms[1] = __ballot_sync(0xffffffffu, ps);
    }

    float csum = 0.f, ssum = 0.f;

    if ((mg[0] | mg[1] | ms[0] | ms[1]) != 0u) {
        float gmax[4] = {0.f,0.f,0.f,0.f};
        float blog[4] = {0.f,0.f,0.f,0.f};
        int   maxj[4] = {-1,-1,-1,-1};
        int   posm = 0, cenm = 0;
        const float fy = (float)y;

        #pragma unroll
        for (int h = 0; h < 2; h++) {
            const float4 abh = h ? ab1 : ab0;
            unsigned m = mg[h];
            while (m) {
                const int src = __ffs(m) - 1; m &= m - 1;
                // broadcast raw annotation, recompute params locally
                const float a0 = __shfl_sync(0xffffffffu, abh.x, src);
                const float a1 = __shfl_sync(0xffffffffu, abh.y, src);
                const float a2 = __shfl_sync(0xffffffffu, abh.z, src);
                const float a3 = __shfl_sync(0xffffffffu, abh.w, src);
                const int x1 = (int)floorf(a0 * inv), y1 = (int)floorf(a1 * inv);
                const int x2 = (int)floorf(a2 * inv), y2 = (int)floorf(a3 * inv);
                const int cx = (x1 + x2) >> 1, cy = (y1 + y2) >> 1;
                const float A = (float)(x1 + cx);
                const float C = -0.5f / sqrt_approx((float)cx*(float)cx + (float)cy*(float)cy);
                const float dy = fy - (float)(y1 + cy);
                const float dy2 = dy * dy;
                const float fx1 = (float)x1, fx2 = (float)x2;
                #pragma unroll
                for (int i = 0; i < 4; i++) {
                    const float fx = fx0 + (float)i;
                    if (fx >= fx1 && fx < fx2) {
                        posm |= (1 << i);
                        const float dx = fx - A;
                        const float d  = sqrt_approx(fmaf(dx, dx, dy2));
                        gmax[i] = fmaxf(gmax[i], __expf(C * d));
                    }
                }
            }
            m = ms[h];
            while (m) {
                const int src = __ffs(m) - 1; m &= m - 1;
                const float a0 = __shfl_sync(0xffffffffu, abh.x, src);
                const float a1 = __shfl_sync(0xffffffffu, abh.y, src);
                const float a2 = __shfl_sync(0xffffffffu, abh.z, src);
                const float a3 = __shfl_sync(0xffffffffu, abh.w, src);
                const int x1 = (int)floorf(a0 * inv), y1 = (int)floorf(a1 * inv);
                const int x2 = (int)floorf(a2 * inv), y2 = (int)floorf(a3 * inv);
                const int cx = (x1 + x2) >> 1, cy = (y1 + y2) >> 1;
                const int dyo = y - cy;
                const int t = cx + dyo - x0;
                if ((unsigned)t <= 3u) {
                    const int k = src + (h << 5);
                    const int j = (dyo + 2) * KB + k;       // last-write-wins order
                    if (j > maxj[t]) { maxj[t] = j; blog[t] = __logf((float)(y2 - y1)); }
                    if (dyo == 0) cenm |= (1 << t);
                }
            }
        }

        const float pv[4] = {cm4.x, cm4.y, cm4.z, cm4.w};
        #pragma unroll
        for (int i = 0; i < 4; i++) {
            const float p = fminf(fmaxf(pv[i], 1e-4f), 0.9999f);
            if (cenm & (1 << i)) {
                const float q = 1.0f - p;
                csum += q * q * (-__logf(p));                    // ALPHA=1, GAMMA=2
            } else if (posm & (1 << i)) {
                float q = 1.0f - gmax[i];
                float wgt = q * q; wgt = wgt * wgt;              // BETA=4
                csum += wgt * p * p * (-__logf(1.0f - p));
            }
            if (maxj[i] >= 0) {
                const float d = fabsf(blog[i] - smap[(size_t)gq * 4 + i]);
                ssum += (d <= 1.0f) ? 0.5f * d * d : (d - 0.5f);
            }
        }
    }

    // ---- block reduce (single barrier, 16 warps) ----
    #pragma unroll
    for (int off = 16; off; off >>= 1) {
        csum += __shfl_down_sync(0xffffffffu, csum, off);
        ssum += __shfl_down_sync(0xffffffffu, ssum, off);
    }
    if (lane == 0) { r_c[w] = csum; r_s[w] = ssum; }
    __syncthreads();
    if (tid < 16) {
        csum = r_c[tid]; ssum = r_s[tid];
        #pragma unroll
        for (int off = 8; off; off >>= 1) {
            csum += __shfl_down_sync(0x0000ffffu, csum, off);
            ssum += __shfl_down_sync(0x0000ffffu, ssum, off);
        }
        if (tid == 0) {
            // fire-and-forget relaxed reductions (RED)
            atomicAdd(&g_acc[0], (double)csum);
            atomicAdd(&g_acc[1], (double)ssum);
            // release-inc: prior REDs visible before the inc is visible
            unsigned old;
            asm volatile("atom.release.gpu.global.inc.u32 %0, [%1], %2;"
                         : "=r"(old)
                         : "l"(&g_cnt), "r"((unsigned)(GRID - 1))
                         : "memory");
            if (old == GRID - 1) {
                double c2, s2;
                asm volatile("ld.acquire.gpu.global.f64 %0, [%1];"
                             : "=d"(c2) : "l"(&g_acc[0]) : "memory");
                asm volatile("ld.acquire.gpu.global.f64 %0, [%1];"
                             : "=d"(s2) : "l"(&g_acc[1]) : "memory");
                out[0] = (float)(c2 * (1.0 / 64.0));
                out[1] = (float)(s2 * (1.0 / 64.0));
                g_acc[0] = 0.0;     // reset for next replay
                g_acc[1] = 0.0;
            }
        }
    }
}

extern "C" void kernel_launch(void* const* d_in, const int* in_sizes, int n_in,
                              void* d_out, int out_size) {
    const float* cm   = (const float*)d_in[0];
    const float* sm   = (const float*)d_in[1];
    const float* ann  = (const float*)d_in[2];
    const void*  strp = (n_in > 3) ? d_in[3] : nullptr;
    float* out = (float*)d_out;

    lz_fused_kernel<<<GRID, TPB>>>(cm, sm, ann, strp, out);
}

// round 12
// speedup vs baseline: 1.2647x; 1.2610x over previous
#include <cuda_runtime.h>
#include <cuda_bf16.h>

#define KB    64      // boxes
#define GRID  128     // block b handles striped rows {b, b+128, b+256, b+384}
#define TPB   1024    // 32 warps: warp w -> row (w>>3), 64-px span (w&7)

__device__ double       g_acc[2] __attribute__((aligned(16)));
__device__ unsigned int g_cnt;      // wraps back to 0 every run (deterministic)

__device__ __forceinline__ float sqrt_approx(float x) {
    float r; asm("sqrt.approx.f32 %0, %1;" : "=f"(r) : "f"(x)); return r;
}

__global__ __launch_bounds__(TPB) void lz_fused_kernel(
    const float* __restrict__ cm,      // center_maps (batch 0 = first 262144)
    const float* __restrict__ smap,    // scale_maps (batch 0)
    const float* __restrict__ ann,     // annotations (batch 0 = 64 float4)
    const void*  __restrict__ stridep, // stride scalar (int32 or float32)
    float* __restrict__ out)
{
    __shared__ float r_c[32], r_s[32];

    const int tid  = threadIdx.x;
    const int b    = blockIdx.x;
    const int lane = tid & 31;
    const int w    = tid >> 5;          // warp 0..31
    const int rr   = w >> 3;            // which striped row
    const int sp   = w & 7;             // 64-px span within row

    const int y    = b + (rr << 7);     // this warp's row
    const int wxa  = sp << 6;           // warp first x
    const int x0   = wxa + (lane << 1); // thread's first pixel
    const float fx0 = (float)x0;
    const int   wxb = wxa + 63;

    // ---- issue ALL independent loads at cycle 0 (3 parallel DRAM round trips) ----
    const int gq = y * 256 + (x0 >> 1);            // float2 index into maps
    const float2 cm2 = ((const float2*)cm)[gq];
    const float2 sm2 = ((const float2*)smap)[gq];  // unconditional: removes serial trip
    const float4 ab0 = ((const float4*)ann)[lane];
    const float4 ab1 = ((const float4*)ann)[lane + 32];

    // ---- stride (uniform tiny load) ----
    float stridef = 4.0f;
    if (stridep) {
        int iv = ((const int*)stridep)[0];
        stridef = (iv > 0 && iv <= 65536) ? (float)iv : __int_as_float(iv);
    }
    const float inv = 1.0f / stridef;

    // ---- each lane owns boxes {lane, lane+32}: predicates + ballots (no smem) ----
    unsigned mg[2], ms[2];
    {
        // half 0
        int x1 = (int)floorf(ab0.x * inv), y1 = (int)floorf(ab0.y * inv);
        int x2 = (int)floorf(ab0.z * inv), y2 = (int)floorf(ab0.w * inv);
        int cx = (x1 + x2) >> 1, cy = (y1 + y2) >> 1, dyo = y - cy;
        bool pg = (y >= y1) && (y < y2) && (x1 <= wxb) && (x2 > wxa);
        bool ps = ((unsigned)(dyo + 2) <= 4u) && ((unsigned)(cx + dyo - wxa) <= 63u);
        mg[0] = __ballot_sync(0xffffffffu, pg);
        ms[0] = __ballot_sync(0xffffffffu, ps);
        // half 1
        x1 = (int)floorf(ab1.x * inv); y1 = (int)floorf(ab1.y * inv);
        x2 = (int)floorf(ab1.z * inv); y2 = (int)floorf(ab1.w * inv);
        cx = (x1 + x2) >> 1; cy = (y1 + y2) >> 1; dyo = y - cy;
        pg = (y >= y1) && (y < y2) && (x1 <= wxb) && (x2 > wxa);
        ps = ((unsigned)(dyo + 2) <= 4u) && ((unsigned)(cx + dyo - wxa) <= 63u);
        mg[1] = __ballot_sync(0xffffffffu, pg);
        ms[1] = __ballot_sync(0xffffffffu, ps);
    }

    float csum = 0.f, ssum = 0.f;

    if ((mg[0] | mg[1] | ms[0] | ms[1]) != 0u) {
        float gmax[2] = {0.f,0.f};
        float blog[2] = {0.f,0.f};
        int   maxj[2] = {-1,-1};
        int   posm = 0, cenm = 0;
        const float fy = (float)y;

        #pragma unroll
        for (int h = 0; h < 2; h++) {
            const float4 abh = h ? ab1 : ab0;
            unsigned m = mg[h];
            while (m) {
                const int src = __ffs(m) - 1; m &= m - 1;
                // broadcast raw annotation, recompute params locally
                const float a0 = __shfl_sync(0xffffffffu, abh.x, src);
                const float a1 = __shfl_sync(0xffffffffu, abh.y, src);
                const float a2 = __shfl_sync(0xffffffffu, abh.z, src);
                const float a3 = __shfl_sync(0xffffffffu, abh.w, src);
                const int x1 = (int)floorf(a0 * inv), y1 = (int)floorf(a1 * inv);
                const int x2 = (int)floorf(a2 * inv), y2 = (int)floorf(a3 * inv);
                const int cx = (x1 + x2) >> 1, cy = (y1 + y2) >> 1;
                const float A = (float)(x1 + cx);
                const float C = -0.5f / sqrt_approx((float)cx*(float)cx + (float)cy*(float)cy);
                const float dy = fy - (float)(y1 + cy);
                const float dy2 = dy * dy;
                const float fx1 = (float)x1, fx2 = (float)x2;
                #pragma unroll
                for (int i = 0; i < 2; i++) {
                    const float fx = fx0 + (float)i;
                    if (fx >= fx1 && fx < fx2) {
                        posm |= (1 << i);
                        const float dx = fx - A;
                        const float d  = sqrt_approx(fmaf(dx, dx, dy2));
                        gmax[i] = fmaxf(gmax[i], __expf(C * d));
                    }
                }
            }
            m = ms[h];
            while (m) {
                const int src = __ffs(m) - 1; m &= m - 1;
                const float a0 = __shfl_sync(0xffffffffu, abh.x, src);
                const float a1 = __shfl_sync(0xffffffffu, abh.y, src);
                const float a2 = __shfl_sync(0xffffffffu, abh.z, src);
                const float a3 = __shfl_sync(0xffffffffu, abh.w, src);
                const int x1 = (int)floorf(a0 * inv), y1 = (int)floorf(a1 * inv);
                const int x2 = (int)floorf(a2 * inv), y2 = (int)floorf(a3 * inv);
                const int cx = (x1 + x2) >> 1, cy = (y1 + y2) >> 1;
                const int dyo = y - cy;
                const int t = cx + dyo - x0;
                if ((unsigned)t <= 1u) {
                    const int k = src + (h << 5);
                    const int j = (dyo + 2) * KB + k;       // last-write-wins order
                    if (j > maxj[t]) { maxj[t] = j; blog[t] = __logf((float)(y2 - y1)); }
                    if (dyo == 0) cenm |= (1 << t);
                }
            }
        }

        const float pv[2] = {cm2.x, cm2.y};
        const float sv[2] = {sm2.x, sm2.y};
        #pragma unroll
        for (int i = 0; i < 2; i++) {
            const float p = fminf(fmaxf(pv[i], 1e-4f), 0.9999f);
            if (cenm & (1 << i)) {
                const float q = 1.0f - p;
                csum += q * q * (-__logf(p));                    // ALPHA=1, GAMMA=2
            } else if (posm & (1 << i)) {
                float q = 1.0f - gmax[i];
                float wgt = q * q; wgt = wgt * wgt;              // BETA=4
                csum += wgt * p * p * (-__logf(1.0f - p));
            }
            if (maxj[i] >= 0) {
                const float d = fabsf(blog[i] - sv[i]);
                ssum += (d <= 1.0f) ? 0.5f * d * d : (d - 0.5f);
            }
        }
    }

    // ---- block reduce (single barrier) ----
    #pragma unroll
    for (int off = 16; off; off >>= 1) {
        csum += __shfl_down_sync(0xffffffffu, csum, off);
        ssum += __shfl_down_sync(0xffffffffu, ssum, off);
    }
    if (lane == 0) { r_c[w] = csum; r_s[w] = ssum; }
    __syncthreads();
    if (tid < 32) {
        csum = r_c[tid]; ssum = r_s[tid];
        #pragma unroll
        for (int off = 16; off; off >>= 1) {
            csum += __shfl_down_sync(0xffffffffu, csum, off);
            ssum += __shfl_down_sync(0xffffffffu, ssum, off);
        }
        if (tid == 0) {
            // fire-and-forget relaxed reductions (RED)
            atomicAdd(&g_acc[0], (double)csum);
            atomicAdd(&g_acc[1], (double)ssum);
            // release-inc: prior REDs visible before the inc is visible
            unsigned old;
            asm volatile("atom.release.gpu.global.inc.u32 %0, [%1], %2;"
                         : "=r"(old)
                         : "l"(&g_cnt), "r"((unsigned)(GRID - 1))
                         : "memory");
            if (old == GRID - 1) {
                // single vector acquire load: one L2 round trip for both sums
                double c2, s2;
                asm volatile("ld.acquire.gpu.global.v2.f64 {%0, %1}, [%2];"
                             : "=d"(c2), "=d"(s2) : "l"(&g_acc[0]) : "memory");
                out[0] = (float)(c2 * (1.0 / 64.0));
                out[1] = (float)(s2 * (1.0 / 64.0));
                g_acc[0] = 0.0;     // reset for next replay
                g_acc[1] = 0.0;
            }
        }
    }
}

extern "C" void kernel_launch(void* const* d_in, const int* in_sizes, int n_in,
                              void* d_out, int out_size) {
    const float* cm   = (const float*)d_in[0];
    const float* sm   = (const float*)d_in[1];
    const float* ann  = (const float*)d_in[2];
    const void*  strp = (n_in > 3) ? d_in[3] : nullptr;
    float* out = (float*)d_out;

    lz_fused_kernel<<<GRID, TPB>>>(cm, sm, ann, strp, out);
}